// round 2
// baseline (speedup 1.0000x reference)
#include <cuda_runtime.h>

#define D_MODEL 32
#define SEQ 128

// A_scaled, C_scaled, alpha, beta
__device__ float g_params[4];

__device__ __forceinline__ float ex2f(float z) {
    float r;
    asm("ex2.approx.f32 %0, %1;" : "=f"(r) : "f"(z));
    return r;
}

// One warp: collapse all weights into 4 scalars.
__global__ void precompute_kernel(const float* __restrict__ Wt, const float* __restrict__ bt,
                                  const float* __restrict__ Wq, const float* __restrict__ bq,
                                  const float* __restrict__ Wk, const float* __restrict__ bk,
                                  const float* __restrict__ Wv, const float* __restrict__ bv,
                                  const float* __restrict__ Wo, const float* __restrict__ bo) {
    int e = threadIdx.x;  // 0..31, one column each
    float qa = 0.f, qb = 0.f, ka = 0.f, kb = 0.f, va = 0.f, vb = 0.f;
#pragma unroll
    for (int d = 0; d < D_MODEL; d++) {
        float wt = Wt[d], btd = bt[d];
        float wq = Wq[d * D_MODEL + e];
        float wk = Wk[d * D_MODEL + e];
        float wv = Wv[d * D_MODEL + e];
        qa = fmaf(wt, wq, qa);  qb = fmaf(btd, wq, qb);
        ka = fmaf(wt, wk, ka);  kb = fmaf(btd, wk, kb);
        va = fmaf(wt, wv, va);  vb = fmaf(btd, wv, vb);
    }
    qb += bq[e];  kb += bk[e];  vb += bv[e];
    float wo = Wo[e];  // Wo is (D_MODEL, 1)

    float A  = qa * ka;   // -> scores coeff of x_q*x_k
    float C  = qb * ka;   // -> scores coeff of x_k
    float al = va * wo;
    float be = vb * wo;
#pragma unroll
    for (int o = 16; o > 0; o >>= 1) {
        A  += __shfl_xor_sync(0xffffffffu, A,  o);
        C  += __shfl_xor_sync(0xffffffffu, C,  o);
        al += __shfl_xor_sync(0xffffffffu, al, o);
        be += __shfl_xor_sync(0xffffffffu, be, o);
    }
    if (e == 0) {
        float inv_scale = 1.0f / sqrtf((float)D_MODEL);
        g_params[0] = A * inv_scale;
        g_params[1] = C * inv_scale;
        g_params[2] = al;
        g_params[3] = be + bo[0];
    }
}

// One CTA per batch row; thread t owns query q = t.
__global__ __launch_bounds__(SEQ) void attn_scalar_kernel(const float* __restrict__ x,
                                                          float* __restrict__ out) {
    __shared__ float sx[SEQ];
    __shared__ float smx[4], smn[4], ssum[4];

    const int b = blockIdx.x;
    const int t = threadIdx.x;
    const int w = t >> 5, l = t & 31;

    float xv = x[(size_t)b * SEQ + t];
    sx[t] = xv;

    // block max/min of x (for softmax stabilization)
    float mx = xv, mn = xv;
#pragma unroll
    for (int o = 16; o > 0; o >>= 1) {
        mx = fmaxf(mx, __shfl_xor_sync(0xffffffffu, mx, o));
        mn = fminf(mn, __shfl_xor_sync(0xffffffffu, mn, o));
    }
    if (l == 0) { smx[w] = mx; smn[w] = mn; }
    __syncthreads();
    mx = fmaxf(fmaxf(smx[0], smx[1]), fmaxf(smx[2], smx[3]));
    mn = fminf(fminf(smn[0], smn[1]), fminf(smn[2], smn[3]));

    const float A = g_params[0], C = g_params[1];
    const float tq = fmaf(A, xv, C);
    // max_k (tq * x_k) depends only on sign of tq
    const float lmax = (tq >= 0.f) ? tq * mx : tq * mn;
    const float L2E = 1.4426950408889634f;
    const float u = tq * L2E;       // logit slope, log2-domain
    const float v = -lmax * L2E;    // stabilization offset, log2-domain

    float num = 0.f, den = 0.f;
    const float4* sx4 = reinterpret_cast<const float4*>(sx);
#pragma unroll 4
    for (int k4 = 0; k4 < SEQ / 4; k4++) {
        float4 xk = sx4[k4];
        float e0 = ex2f(fmaf(u, xk.x, v));
        float e1 = ex2f(fmaf(u, xk.y, v));
        float e2 = ex2f(fmaf(u, xk.z, v));
        float e3 = ex2f(fmaf(u, xk.w, v));
        den += e0; num = fmaf(e0, xk.x, num);
        den += e1; num = fmaf(e1, xk.y, num);
        den += e2; num = fmaf(e2, xk.z, num);
        den += e3; num = fmaf(e3, xk.w, num);
    }
    float m = __fdividef(num, den);  // m_q = softmax-weighted mean of x

    // block sum of m_q
#pragma unroll
    for (int o = 16; o > 0; o >>= 1)
        m += __shfl_xor_sync(0xffffffffu, m, o);
    if (l == 0) ssum[w] = m;
    __syncthreads();
    if (t == 0) {
        float s = (ssum[0] + ssum[1] + ssum[2] + ssum[3]) * (1.0f / (float)SEQ);
        out[b] = fmaf(g_params[2], s, g_params[3]);
    }
}

extern "C" void kernel_launch(void* const* d_in, const int* in_sizes, int n_in,
                              void* d_out, int out_size) {
    const float* x  = (const float*)d_in[0];
    const float* Wt = (const float*)d_in[1];
    const float* bt = (const float*)d_in[2];
    const float* Wq = (const float*)d_in[3];
    const float* bq = (const float*)d_in[4];
    const float* Wk = (const float*)d_in[5];
    const float* bk = (const float*)d_in[6];
    const float* Wv = (const float*)d_in[7];
    const float* bv = (const float*)d_in[8];
    const float* Wo = (const float*)d_in[9];
    const float* bo = (const float*)d_in[10];
    float* out = (float*)d_out;

    const int B = in_sizes[0] / SEQ;

    precompute_kernel<<<1, 32>>>(Wt, bt, Wq, bq, Wk, bk, Wv, bv, Wo, bo);
    attn_scalar_kernel<<<B, SEQ>>>(x, out);
}